// round 6
// baseline (speedup 1.0000x reference)
#include <cuda_runtime.h>
#include <cuda_bf16.h>
#include <math.h>

#define B_SZ   16
#define C_IN   64
#define HH     256
#define WW     256
#define CKK    576
#define FC_DIM 512
#define IMG_PIX (HH * WW)
#define N_IMG  (B_SZ * C_IN)
#define FOUT_ELEMS ((size_t)N_IMG * IMG_PIX)

// Split-K partials (deterministic: fixed summation order)
__device__ float g_h_part[8][B_SZ * CKK];   // layer1 partials (kc0 includes b1)
__device__ float g_l_part[4][B_SZ * CKK];   // layer2 partials (kc0 includes b2)
__device__ float g_kw[B_SZ * CKK];          // softmaxed kernel weights
__device__ unsigned int g_cnt[B_SZ];        // arrival counters (self-resetting)

// ---------------------------------------------------------------------------
// Layer 1 partial: kc-th 64-slice of h = Fc@W1 (+b1 on kc==0).
// grid (3, 128): y = b*8 + kc. 192 threads. Fully unrolled -> all loads in flight.
// ---------------------------------------------------------------------------
__global__ __launch_bounds__(192) void EKG_mlp1_part(
    const float* __restrict__ Fc,
    const float* __restrict__ W1, const float* __restrict__ b1)
{
    __shared__ float sin_[64];
    const int b  = blockIdx.y >> 3;
    const int kc = blockIdx.y & 7;
    const int j  = blockIdx.x * 192 + threadIdx.x;
    const int i0 = kc * 64;

    if (threadIdx.x < 64) sin_[threadIdx.x] = Fc[b * FC_DIM + i0 + threadIdx.x];
    __syncthreads();

    float a0 = 0.f, a1 = 0.f, a2 = 0.f, a3 = 0.f;
    const float* __restrict__ wp = W1 + (size_t)i0 * CKK + j;
    #pragma unroll
    for (int i = 0; i < 64; i += 4) {
        a0 = fmaf(sin_[i + 0], wp[(i + 0) * CKK], a0);
        a1 = fmaf(sin_[i + 1], wp[(i + 1) * CKK], a1);
        a2 = fmaf(sin_[i + 2], wp[(i + 2) * CKK], a2);
        a3 = fmaf(sin_[i + 3], wp[(i + 3) * CKK], a3);
    }
    float acc = (a0 + a1) + (a2 + a3);
    if (kc == 0) acc += b1[j];
    g_h_part[kc][b * CKK + j] = acc;
}

// ---------------------------------------------------------------------------
// Layer 2 partial + fused softmax (last arriving block per batch does it).
// grid (3, 64): y = b*4 + kc. 192 threads.
// ---------------------------------------------------------------------------
__global__ __launch_bounds__(192) void EKG_mlp2_fused(
    const float* __restrict__ W2, const float* __restrict__ b2,
    float* __restrict__ kw_tail, int write_tail)
{
    __shared__ float sh[144];
    __shared__ float red[8];
    __shared__ float bcast;
    __shared__ unsigned int s_old;

    const int b  = blockIdx.y >> 2;
    const int kc = blockIdx.y & 3;
    const int j  = blockIdx.x * 192 + threadIdx.x;
    const int i0 = kc * 144;
    const int tid = threadIdx.x;
    const int lane = tid & 31;
    const int wid  = tid >> 5;      // 0..5

    if (tid < 144) {
        const int idx = b * CKK + i0 + tid;
        float h = (((g_h_part[0][idx] + g_h_part[1][idx]) +
                    (g_h_part[2][idx] + g_h_part[3][idx])) +
                   ((g_h_part[4][idx] + g_h_part[5][idx]) +
                    (g_h_part[6][idx] + g_h_part[7][idx])));
        sh[tid] = fmaxf(h, 0.0f);
    }
    __syncthreads();

    float a0 = 0.f, a1 = 0.f, a2 = 0.f, a3 = 0.f;
    const float* __restrict__ wp = W2 + (size_t)i0 * CKK + j;
    #pragma unroll
    for (int i = 0; i < 144; i += 4) {
        a0 = fmaf(sh[i + 0], wp[(i + 0) * CKK], a0);
        a1 = fmaf(sh[i + 1], wp[(i + 1) * CKK], a1);
        a2 = fmaf(sh[i + 2], wp[(i + 2) * CKK], a2);
        a3 = fmaf(sh[i + 3], wp[(i + 3) * CKK], a3);
    }
    float acc = (a0 + a1) + (a2 + a3);
    if (kc == 0) acc += b2[j];
    g_l_part[kc][b * CKK + j] = acc;

    // make partial visible, then count arrival
    __threadfence();
    __syncthreads();
    if (tid == 0) s_old = atomicAdd(&g_cnt[b], 1u);
    __syncthreads();
    if (s_old != 11u) return;       // not the last of the 12 blocks for batch b
    __threadfence();                // acquire: other blocks' partials now visible

    // ---- softmax over 576 logits, 192 threads x 3 each ----
    float lg[3];
    float lmax = -INFINITY;
    #pragma unroll
    for (int t = 0; t < 3; ++t) {
        const int idx = b * CKK + tid + 192 * t;
        lg[t] = ((g_l_part[0][idx] + g_l_part[1][idx]) +
                 (g_l_part[2][idx] + g_l_part[3][idx]));
        lmax = fmaxf(lmax, lg[t]);
    }
    #pragma unroll
    for (int o = 16; o > 0; o >>= 1)
        lmax = fmaxf(lmax, __shfl_xor_sync(0xffffffffu, lmax, o));
    if (lane == 0) red[wid] = lmax;
    __syncthreads();
    if (wid == 0) {
        float v = (lane < 6) ? red[lane] : -INFINITY;
        #pragma unroll
        for (int o = 4; o > 0; o >>= 1)
            v = fmaxf(v, __shfl_xor_sync(0xffffffffu, v, o));
        if (lane == 0) bcast = v;
    }
    __syncthreads();
    const float maxv = bcast;

    float e[3];
    float lsum = 0.f;
    #pragma unroll
    for (int t = 0; t < 3; ++t) { e[t] = expf(lg[t] - maxv); lsum += e[t]; }
    #pragma unroll
    for (int o = 16; o > 0; o >>= 1)
        lsum += __shfl_xor_sync(0xffffffffu, lsum, o);
    __syncthreads();
    if (lane == 0) red[wid] = lsum;
    __syncthreads();
    if (wid == 0) {
        float v = (lane < 6) ? red[lane] : 0.0f;
        #pragma unroll
        for (int o = 4; o > 0; o >>= 1)
            v += __shfl_xor_sync(0xffffffffu, v, o);
        if (lane == 0) bcast = v;
    }
    __syncthreads();
    const float inv = 1.0f / bcast;

    #pragma unroll
    for (int t = 0; t < 3; ++t) {
        const int idx = b * CKK + tid + 192 * t;
        const float kw = e[t] * inv;
        g_kw[idx] = kw;
        if (write_tail) kw_tail[idx] = kw;
    }

    // reset counter for next graph replay
    if (tid == 0) g_cnt[b] = 0u;
}

// ---------------------------------------------------------------------------
// Depthwise 3x3 conv, reflect pad, no smem. Neighbors via warp shuffle.
// Block 256: tx 0..63 (float4 col group), ty 0..3 (strip of 8 rows).
// Block tile 256x32. Grid (8, 1024).
// ---------------------------------------------------------------------------
#define ROWS_PER_BLOCK 32
#define ROWS_PER_THREAD 8

__device__ __forceinline__ void load_row6(
    const float* __restrict__ img, int gr, int tx, int lane, float* __restrict__ w)
{
    gr = (gr < 0) ? 1 : ((gr > HH - 1) ? (2 * HH - 2 - gr) : gr);
    const float* rowp = img + gr * WW;
    const float4 q = __ldg((const float4*)rowp + tx);
    float left  = __shfl_up_sync(0xffffffffu, q.w, 1);
    float right = __shfl_down_sync(0xffffffffu, q.x, 1);
    if (lane == 0)  left  = (tx == 0)  ? q.y : __ldg(rowp + 4 * tx - 1);
    if (lane == 31) right = (tx == 63) ? q.z : __ldg(rowp + 4 * tx + 4);
    w[0] = left; w[1] = q.x; w[2] = q.y; w[3] = q.z; w[4] = q.w; w[5] = right;
}

__global__ __launch_bounds__(256) void EKG_conv_kernel(
    const float* __restrict__ Fd,
    float* __restrict__ out)
{
    const int bc   = blockIdx.y;
    const int tid  = threadIdx.x;
    const int tx   = tid & 63;
    const int lane = tid & 31;
    const int ty   = tid >> 6;
    const int rbase = blockIdx.x * ROWS_PER_BLOCK + ty * ROWS_PER_THREAD;

    const float* __restrict__ img = Fd  + (size_t)bc * IMG_PIX;
    float*       __restrict__ o   = out + (size_t)bc * IMG_PIX;

    const float* kwp = g_kw + bc * 9;
    const float w00 = __ldg(kwp+0), w01 = __ldg(kwp+1), w02 = __ldg(kwp+2);
    const float w10 = __ldg(kwp+3), w11 = __ldg(kwp+4), w12 = __ldg(kwp+5);
    const float w20 = __ldg(kwp+6), w21 = __ldg(kwp+7), w22 = __ldg(kwp+8);

    float win[3][6];
    load_row6(img, rbase - 1, tx, lane, win[0]);
    load_row6(img, rbase + 0, tx, lane, win[1]);

    #pragma unroll
    for (int rr = 0; rr < ROWS_PER_THREAD; ++rr) {
        load_row6(img, rbase + rr + 1, tx, lane, win[(rr + 2) % 3]);

        const float* T  = win[rr % 3];
        const float* M  = win[(rr + 1) % 3];
        const float* Bt = win[(rr + 2) % 3];

        float4 r;
        r.x = w00*T[0]; r.x = fmaf(w01,T[1],r.x); r.x = fmaf(w02,T[2],r.x);
        r.x = fmaf(w10,M[0],r.x); r.x = fmaf(w11,M[1],r.x); r.x = fmaf(w12,M[2],r.x);
        r.x = fmaf(w20,Bt[0],r.x); r.x = fmaf(w21,Bt[1],r.x); r.x = fmaf(w22,Bt[2],r.x);

        r.y = w00*T[1]; r.y = fmaf(w01,T[2],r.y); r.y = fmaf(w02,T[3],r.y);
        r.y = fmaf(w10,M[1],r.y); r.y = fmaf(w11,M[2],r.y); r.y = fmaf(w12,M[3],r.y);
        r.y = fmaf(w20,Bt[1],r.y); r.y = fmaf(w21,Bt[2],r.y); r.y = fmaf(w22,Bt[3],r.y);

        r.z = w00*T[2]; r.z = fmaf(w01,T[3],r.z); r.z = fmaf(w02,T[4],r.z);
        r.z = fmaf(w10,M[2],r.z); r.z = fmaf(w11,M[3],r.z); r.z = fmaf(w12,M[4],r.z);
        r.z = fmaf(w20,Bt[2],r.z); r.z = fmaf(w21,Bt[3],r.z); r.z = fmaf(w22,Bt[4],r.z);

        r.w = w00*T[3]; r.w = fmaf(w01,T[4],r.w); r.w = fmaf(w02,T[5],r.w);
        r.w = fmaf(w10,M[3],r.w); r.w = fmaf(w11,M[4],r.w); r.w = fmaf(w12,M[5],r.w);
        r.w = fmaf(w20,Bt[3],r.w); r.w = fmaf(w21,Bt[4],r.w); r.w = fmaf(w22,Bt[5],r.w);

        __stcs((float4*)(o + (size_t)(rbase + rr) * WW + 4 * tx), r);
    }
}

// ---------------------------------------------------------------------------
extern "C" void kernel_launch(void* const* d_in, const int* in_sizes, int n_in,
                              void* d_out, int out_size) {
    const float* Fd = (const float*)d_in[0];
    const float* Fc = (const float*)d_in[1];
    const float* W1 = (const float*)d_in[2];
    const float* b1 = (const float*)d_in[3];
    const float* W2 = (const float*)d_in[4];
    const float* b2 = (const float*)d_in[5];
    float* out = (float*)d_out;

    const int write_tail = ((size_t)out_size >= FOUT_ELEMS + (size_t)B_SZ * CKK) ? 1 : 0;
    float* kw_tail = out + FOUT_ELEMS;

    EKG_mlp1_part<<<dim3(3, B_SZ * 8), 192>>>(Fc, W1, b1);
    EKG_mlp2_fused<<<dim3(3, B_SZ * 4), 192>>>(W2, b2, kw_tail, write_tail);

    dim3 grid(HH / ROWS_PER_BLOCK, N_IMG);
    EKG_conv_kernel<<<grid, 256>>>(Fd, out);
}